// round 1
// baseline (speedup 1.0000x reference)
#include <cuda_runtime.h>

// Problem constants
#define BB 2
#define SS 2048
#define DM 1024
#define HH 16
#define DK 64

// Scratch (allocation-free rule: __device__ globals)
__device__ float g_qh[BB*HH*SS*DK];   // 16 MB, [B,H,S,64]
__device__ float g_kh[BB*HH*SS*DK];   // 16 MB
__device__ float g_vh[BB*HH*SS*DK];   // 16 MB
__device__ float g_attn[BB*SS*DM];    // 16 MB, [B,S,D]

// ---------------------------------------------------------------------------
// 64x64 tile GEMM: C[M,N] = A[M,K] @ W[N,K]^T + bias,   K = 1024 fixed.
// 256 threads, each computes a 4x4 micro-tile. Smem transposed (k-major) so
// the inner loop is 2x LDS.128 + 16 FFMA per k-step.
// ---------------------------------------------------------------------------
__device__ __forceinline__ void gemm64(const float* __restrict__ A,
                                       const float* __restrict__ W,
                                       const float* __restrict__ bias,
                                       float* __restrict__ C,
                                       bool splitHead)
{
    __shared__ float As[16][68];
    __shared__ float Ws[16][68];

    const int tid = threadIdx.x;
    const int ty  = tid >> 4;        // 0..15
    const int tx  = tid & 15;        // 0..15
    const int m0  = blockIdx.y << 6;
    const int n0  = blockIdx.x << 6;
    const int lr  = tid >> 2;        // 0..63 (tile row loaded by this thread)
    const int lk  = (tid & 3) << 2;  // 0,4,8,12 (k sub-offset)

    float acc[4][4];
#pragma unroll
    for (int i = 0; i < 4; i++)
#pragma unroll
        for (int j = 0; j < 4; j++) acc[i][j] = 0.f;

    const float* Ap = A + (size_t)(m0 + lr) * 1024 + lk;
    const float* Wp = W + (size_t)(n0 + lr) * 1024 + lk;

    for (int k0 = 0; k0 < 1024; k0 += 16) {
        float4 av = *(const float4*)(Ap + k0);
        float4 wv = *(const float4*)(Wp + k0);
        As[lk + 0][lr] = av.x; As[lk + 1][lr] = av.y;
        As[lk + 2][lr] = av.z; As[lk + 3][lr] = av.w;
        Ws[lk + 0][lr] = wv.x; Ws[lk + 1][lr] = wv.y;
        Ws[lk + 2][lr] = wv.z; Ws[lk + 3][lr] = wv.w;
        __syncthreads();

#pragma unroll
        for (int kk = 0; kk < 16; kk++) {
            float4 a = *(const float4*)&As[kk][ty << 2];
            float4 b = *(const float4*)&Ws[kk][tx << 2];
            float ar[4] = {a.x, a.y, a.z, a.w};
            float br[4] = {b.x, b.y, b.z, b.w};
#pragma unroll
            for (int i = 0; i < 4; i++)
#pragma unroll
                for (int j = 0; j < 4; j++)
                    acc[i][j] += ar[i] * br[j];
        }
        __syncthreads();
    }

#pragma unroll
    for (int i = 0; i < 4; i++) {
        const int m = m0 + (ty << 2) + i;
#pragma unroll
        for (int j = 0; j < 4; j++) {
            const int n = n0 + (tx << 2) + j;
            float val = acc[i][j] + bias[n];
            if (splitHead) {
                // write to [B,H,S,64]
                const int b = m >> 11;          // m / S
                const int s = m & 2047;         // m % S
                const int h = n >> 6;           // n / 64
                const int d = n & 63;           // n % 64
                C[(((size_t)(b * HH + h) * SS) + s) * DK + d] = val;
            } else {
                C[(size_t)m * 1024 + n] = val;
            }
        }
    }
}

__global__ void __launch_bounds__(256)
qkv_proj_kernel(const float* __restrict__ q, const float* __restrict__ k,
                const float* __restrict__ v,
                const float* __restrict__ wq, const float* __restrict__ wk,
                const float* __restrict__ wv,
                const float* __restrict__ bq, const float* __restrict__ bk,
                const float* __restrict__ bv)
{
    const float *A, *W, *bias;
    float* C;
    if (blockIdx.z == 0)      { A = q; W = wq; bias = bq; C = g_qh; }
    else if (blockIdx.z == 1) { A = k; W = wk; bias = bk; C = g_kh; }
    else                      { A = v; W = wv; bias = bv; C = g_vh; }
    gemm64(A, W, bias, C, true);
}

__global__ void __launch_bounds__(256)
out_proj_kernel(const float* __restrict__ wo, const float* __restrict__ bo,
                float* __restrict__ out)
{
    gemm64(g_attn, wo, bo, out, false);
}

// ---------------------------------------------------------------------------
// Flash attention: one CTA per (q-block of 64, head, batch).
// Br = Bc = 64, d_k = 64, 32 KV tiles. 256 threads, 4x4 micro-tiles.
// Score cols use c = tx + 16*j (conflict-free strided smem reads),
// O/V cols use d = 4*tx + j (LDS.128). Pt aliases Ks smem.
// ---------------------------------------------------------------------------
__global__ void __launch_bounds__(256, 2)
flash_kernel(const int* __restrict__ mask)
{
    extern __shared__ float sm[];
    float* Qs = sm;                  // [64][64] row-major
    float* Ks = sm + 64 * 64;        // [64][68] row-major (aliased as Pt)
    float* Vs = Ks + 64 * 68;        // [64][64] row-major

    const int b  = blockIdx.z;
    const int h  = blockIdx.y;
    const int q0 = blockIdx.x << 6;
    const int tid = threadIdx.x;
    const int ty = tid >> 4;   // 0..15
    const int tx = tid & 15;   // 0..15

    const float* Qg = g_qh + ((size_t)(b * HH + h) * SS + q0) * DK;
    const float* Kg = g_kh + ((size_t)(b * HH + h) * SS) * DK;
    const float* Vg = g_vh + ((size_t)(b * HH + h) * SS) * DK;

    // Load Q tile (vectorized, coalesced)
    {
        const int r  = tid >> 4;          // 0..15
        const int dq = (tid & 15) << 2;   // 0..60 step 4
#pragma unroll
        for (int it = 0; it < 4; it++) {
            const int rr = r + (it << 4);
            *(float4*)&Qs[rr * 64 + dq] = *(const float4*)&Qg[(size_t)rr * 64 + dq];
        }
    }

    float o[4][4];
#pragma unroll
    for (int i = 0; i < 4; i++)
#pragma unroll
        for (int j = 0; j < 4; j++) o[i][j] = 0.f;
    float mrun[4] = {-3e38f, -3e38f, -3e38f, -3e38f};
    float lrun[4] = {0.f, 0.f, 0.f, 0.f};

    for (int t = 0; t < 32; t++) {
        const int k0 = t << 6;
        __syncthreads();  // previous tile's Pt/Vs readers done (also covers Qs on t=0)

        // Load K,V tiles
        {
            const int r  = tid >> 4;
            const int dq = (tid & 15) << 2;
#pragma unroll
            for (int it = 0; it < 4; it++) {
                const int rr = r + (it << 4);
                *(float4*)&Ks[rr * 68 + dq] = *(const float4*)&Kg[(size_t)(k0 + rr) * 64 + dq];
                *(float4*)&Vs[rr * 64 + dq] = *(const float4*)&Vg[(size_t)(k0 + rr) * 64 + dq];
            }
        }
        __syncthreads();

        // Preload mask for this thread's 16 score elements
        int mv[4][4];
#pragma unroll
        for (int i = 0; i < 4; i++) {
            const int mrow = q0 + ty + (i << 4);
#pragma unroll
            for (int j = 0; j < 4; j++)
                mv[i][j] = mask[(size_t)mrow * SS + (k0 + tx + (j << 4))];
        }

        // S = Q @ K^T
        float s[4][4];
#pragma unroll
        for (int i = 0; i < 4; i++)
#pragma unroll
            for (int j = 0; j < 4; j++) s[i][j] = 0.f;

#pragma unroll
        for (int dq4 = 0; dq4 < 64; dq4 += 4) {
            float4 qv[4], kv[4];
#pragma unroll
            for (int i = 0; i < 4; i++)
                qv[i] = *(const float4*)&Qs[(ty + (i << 4)) * 64 + dq4];
#pragma unroll
            for (int j = 0; j < 4; j++)
                kv[j] = *(const float4*)&Ks[(tx + (j << 4)) * 68 + dq4];
#pragma unroll
            for (int i = 0; i < 4; i++)
#pragma unroll
                for (int j = 0; j < 4; j++)
                    s[i][j] += qv[i].x * kv[j].x + qv[i].y * kv[j].y +
                               qv[i].z * kv[j].z + qv[i].w * kv[j].w;
        }

        // scale + mask
#pragma unroll
        for (int i = 0; i < 4; i++)
#pragma unroll
            for (int j = 0; j < 4; j++)
                s[i][j] = mv[i][j] ? s[i][j] * 0.125f : -1e9f;

        // Online softmax (row reduction over the 16 tx lanes of the half-warp)
#pragma unroll
        for (int i = 0; i < 4; i++) {
            float mx = fmaxf(fmaxf(s[i][0], s[i][1]), fmaxf(s[i][2], s[i][3]));
#pragma unroll
            for (int off = 1; off < 16; off <<= 1)
                mx = fmaxf(mx, __shfl_xor_sync(0xffffffffu, mx, off));
            const float mn = fmaxf(mrun[i], mx);
            const float alpha = __expf(mrun[i] - mn);
            mrun[i] = mn;
            float r0 = 0.f;
#pragma unroll
            for (int j = 0; j < 4; j++) {
                s[i][j] = __expf(s[i][j] - mn);
                r0 += s[i][j];
            }
#pragma unroll
            for (int off = 1; off < 16; off <<= 1)
                r0 += __shfl_xor_sync(0xffffffffu, r0, off);
            lrun[i] = lrun[i] * alpha + r0;
#pragma unroll
            for (int jj = 0; jj < 4; jj++) o[i][jj] *= alpha;
        }

        __syncthreads();  // all threads done reading Ks before aliasing as Pt
        float* Pt = Ks;   // [64 rows (q)][68 stride], col = kv index
#pragma unroll
        for (int i = 0; i < 4; i++)
#pragma unroll
            for (int j = 0; j < 4; j++)
                Pt[(ty + (i << 4)) * 68 + (tx + (j << 4))] = s[i][j];
        __syncthreads();

        // O += P @ V   (d columns = 4*tx + jj, LDS.128 on both operands)
#pragma unroll
        for (int jq = 0; jq < 64; jq += 4) {
            float4 pv[4], vv[4];
#pragma unroll
            for (int i = 0; i < 4; i++)
                pv[i] = *(const float4*)&Pt[(ty + (i << 4)) * 68 + jq];
#pragma unroll
            for (int u = 0; u < 4; u++)
                vv[u] = *(const float4*)&Vs[(jq + u) * 64 + (tx << 2)];
#pragma unroll
            for (int i = 0; i < 4; i++) {
                o[i][0] += pv[i].x * vv[0].x + pv[i].y * vv[1].x + pv[i].z * vv[2].x + pv[i].w * vv[3].x;
                o[i][1] += pv[i].x * vv[0].y + pv[i].y * vv[1].y + pv[i].z * vv[2].y + pv[i].w * vv[3].y;
                o[i][2] += pv[i].x * vv[0].z + pv[i].y * vv[1].z + pv[i].z * vv[2].z + pv[i].w * vv[3].z;
                o[i][3] += pv[i].x * vv[0].w + pv[i].y * vv[1].w + pv[i].z * vv[2].w + pv[i].w * vv[3].w;
            }
        }
    }

    // Write O / l to g_attn in [B,S,D] layout (merging heads)
    float* Og = g_attn + ((size_t)b * SS + q0) * DM + h * DK;
#pragma unroll
    for (int i = 0; i < 4; i++) {
        const float inv = 1.0f / lrun[i];
        const int r = ty + (i << 4);
#pragma unroll
        for (int jj = 0; jj < 4; jj++)
            Og[(size_t)r * DM + (tx << 2) + jj] = o[i][jj] * inv;
    }
}

// ---------------------------------------------------------------------------
extern "C" void kernel_launch(void* const* d_in, const int* in_sizes, int n_in,
                              void* d_out, int out_size)
{
    const float* q    = (const float*)d_in[0];
    const float* k    = (const float*)d_in[1];
    const float* v    = (const float*)d_in[2];
    const int*   mask = (const int*)  d_in[3];
    const float* wq   = (const float*)d_in[4];
    const float* bq   = (const float*)d_in[5];
    const float* wk   = (const float*)d_in[6];
    const float* bk   = (const float*)d_in[7];
    const float* wv   = (const float*)d_in[8];
    const float* bv   = (const float*)d_in[9];
    const float* wo   = (const float*)d_in[10];
    const float* bo   = (const float*)d_in[11];
    float* out = (float*)d_out;

    const int FLASH_SMEM = (64 * 64 + 64 * 68 + 64 * 64) * 4;  // 50176 B
    cudaFuncSetAttribute(flash_kernel, cudaFuncAttributeMaxDynamicSharedMemorySize,
                         FLASH_SMEM);

    dim3 blk(256);
    // QKV projections: M=4096, N=1024 in 64x64 tiles; z selects q/k/v
    qkv_proj_kernel<<<dim3(16, 64, 3), blk>>>(q, k, v, wq, wk, wv, bq, bk, bv);
    // Flash attention: (32 q-blocks, 16 heads, 2 batches)
    flash_kernel<<<dim3(32, 16, 2), blk, FLASH_SMEM>>>(mask);
    // Output projection
    out_proj_kernel<<<dim3(16, 64, 1), blk>>>(wo, bo, out);
}